// round 1
// baseline (speedup 1.0000x reference)
#include <cuda_runtime.h>
#include <cstdint>
#include <cstddef>

// Problem constants
#define NB 16
#define NP 4096
#define NS 1024
#define NK 16
#define NF 256
#define NO 512
#define NPTS (NB*NP)   // 65536
#define NQ   (NB*NS)   // 16384
#define SEG  4
#define PSEG (NP/SEG)  // 1024

#define POS_INF __int_as_float(0x7f800000)
#define NEG_INF __int_as_float(0xff800000)

// ------------------------- scratch (static device globals) -------------------
__device__ float g_h[(size_t)NPTS * NO];      // 128MB: h = XW + b
__device__ float g_hn[NPTS];                  // 0.5*|x|^2 per point (feature space)
__device__ int   g_fps[NQ];                   // global fps indices
__device__ float g_part[2 * 128 * NO];        // column partial sums / sumsq
__device__ float g_a[NO];                     // BN scale  a = gamma*rsqrt(var+eps)
__device__ float g_c[NO];                     // BN shift  c = beta - mu*a
__device__ float g_knnv[(size_t)NQ * SEG * NK];
__device__ int   g_knni[(size_t)NQ * SEG * NK];
__device__ int   g_nn[(size_t)NQ * NK];

// ------------------------- FPS: one block per cloud --------------------------
// Bit-exact vs jax reference: d = (dx*dx + dy*dy) + dz*dz with RN mul/add
// (no FMA contraction), fminf accumulation, argmax with first-index tiebreak.
__global__ __launch_bounds__(512) void fps_kernel(const float* __restrict__ positions,
                                                  const int* __restrict__ batch,
                                                  float* __restrict__ out_pos,
                                                  float* __restrict__ out_batch) {
    extern __shared__ float sm[];
    float* spos  = sm;                          // NP*3 floats
    int*   sel   = (int*)(spos + NP * 3);       // NS
    float* rv    = (float*)(sel + NS);          // 16
    int*   ri    = (int*)(rv + 16);             // 16
    int*   slast = ri + 16;                     // 1

    const int cloud = blockIdx.x;
    const int tid = threadIdx.x;
    const float* pos = positions + (size_t)cloud * NP * 3;

    for (int i = tid; i < NP * 3; i += 512) spos[i] = pos[i];
    __syncthreads();

    const int PPT = NP / 512;  // 8 points per thread
    float px[8], py[8], pz[8], md[8];
#pragma unroll
    for (int j = 0; j < PPT; j++) {
        int pt = tid + j * 512;
        px[j] = spos[pt * 3 + 0];
        py[j] = spos[pt * 3 + 1];
        pz[j] = spos[pt * 3 + 2];
        md[j] = POS_INF;
    }
    if (tid == 0) sel[0] = 0;
    int last = 0;
    const int lane = tid & 31, warp = tid >> 5;

    for (int it = 1; it < NS; it++) {
        float lx = spos[last * 3 + 0];
        float ly = spos[last * 3 + 1];
        float lz = spos[last * 3 + 2];
        float bv = NEG_INF;
        int bi = 0x7fffffff;
#pragma unroll
        for (int j = 0; j < PPT; j++) {
            float dx = px[j] - lx, dy = py[j] - ly, dz = pz[j] - lz;
            float d = __fadd_rn(__fadd_rn(__fmul_rn(dx, dx), __fmul_rn(dy, dy)),
                                __fmul_rn(dz, dz));
            float m = fminf(md[j], d);
            md[j] = m;
            // pt ascends with j -> strict > keeps smallest index on in-thread tie
            if (m > bv) { bv = m; bi = tid + j * 512; }
        }
#pragma unroll
        for (int off = 16; off > 0; off >>= 1) {
            float ov = __shfl_down_sync(0xffffffffu, bv, off);
            int   oi = __shfl_down_sync(0xffffffffu, bi, off);
            if (ov > bv || (ov == bv && oi < bi)) { bv = ov; bi = oi; }
        }
        if (lane == 0) { rv[warp] = bv; ri[warp] = bi; }
        __syncthreads();
        if (tid == 0) {
            float v = rv[0]; int b = ri[0];
#pragma unroll
            for (int w = 1; w < 16; w++) {
                if (rv[w] > v || (rv[w] == v && ri[w] < b)) { v = rv[w]; b = ri[w]; }
            }
            sel[it] = b;
            slast[0] = b;
        }
        __syncthreads();
        last = slast[0];
    }

    // Emit fps indices + sampled positions + batch (as float)
    for (int s = tid; s < NS; s += 512) {
        int loc = sel[s];
        int g = cloud * NP + loc;
        int oq = cloud * NS + s;
        g_fps[oq] = g;
        out_pos[oq * 3 + 0] = spos[loc * 3 + 0];
        out_pos[oq * 3 + 1] = spos[loc * 3 + 1];
        out_pos[oq * 3 + 2] = spos[loc * 3 + 2];
        out_batch[oq] = (float)batch[g];
    }
}

// ------------------------- 0.5*|x|^2 per point (feature space) ---------------
__global__ __launch_bounds__(128) void xnorm_kernel(const float* __restrict__ feat) {
    int row = blockIdx.x * 4 + (threadIdx.x >> 5);
    int lane = threadIdx.x & 31;
    const float* f = feat + (size_t)row * NF;
    float s = 0.f;
#pragma unroll
    for (int i = 0; i < NF / 32; i++) {
        float v = f[lane + 32 * i];
        s = fmaf(v, v, s);
    }
#pragma unroll
    for (int off = 16; off > 0; off >>= 1) s += __shfl_down_sync(0xffffffffu, s, off);
    if (lane == 0) g_hn[row] = 0.5f * s;
}

// ------------------------- SGEMM h = X*W + b  (fp32, 128x128x8) --------------
__global__ __launch_bounds__(256) void gemm_h_kernel(const float* __restrict__ A,
                                                     const float* __restrict__ W,
                                                     const float* __restrict__ bias) {
    __shared__ float As[8][128];
    __shared__ float Bs[8][128];
    const int bx = blockIdx.x;  // 0..3   (N tiles)
    const int by = blockIdx.y;  // 0..511 (M tiles)
    const int tid = threadIdx.x;
    const int tx = tid & 15, ty = tid >> 4;
    const float* Ab = A + (size_t)by * 128 * NF;
    const int arow = tid >> 1, acol = (tid & 1) * 4;
    const int brow = tid >> 5, bcol = (tid & 31) * 4;

    float acc[8][8];
#pragma unroll
    for (int i = 0; i < 8; i++)
#pragma unroll
        for (int j = 0; j < 8; j++) acc[i][j] = 0.f;

    for (int kb = 0; kb < NF; kb += 8) {
        float4 av = *(const float4*)(Ab + (size_t)arow * NF + kb + acol);
        As[acol + 0][arow] = av.x;
        As[acol + 1][arow] = av.y;
        As[acol + 2][arow] = av.z;
        As[acol + 3][arow] = av.w;
        float4 bv = *(const float4*)(W + (size_t)(kb + brow) * NO + bx * 128 + bcol);
        *(float4*)&Bs[brow][bcol] = bv;
        __syncthreads();
#pragma unroll
        for (int k = 0; k < 8; k++) {
            float4 a0 = *(const float4*)&As[k][ty * 8];
            float4 a1 = *(const float4*)&As[k][ty * 8 + 4];
            float4 b0 = *(const float4*)&Bs[k][tx * 8];
            float4 b1 = *(const float4*)&Bs[k][tx * 8 + 4];
            float ar[8] = {a0.x, a0.y, a0.z, a0.w, a1.x, a1.y, a1.z, a1.w};
            float br[8] = {b0.x, b0.y, b0.z, b0.w, b1.x, b1.y, b1.z, b1.w};
#pragma unroll
            for (int i = 0; i < 8; i++)
#pragma unroll
                for (int j = 0; j < 8; j++) acc[i][j] = fmaf(ar[i], br[j], acc[i][j]);
        }
        __syncthreads();
    }

    const int ccol = bx * 128 + tx * 8;
    const int crow = by * 128 + ty * 8;
    float4 bb0 = *(const float4*)(bias + ccol);
    float4 bb1 = *(const float4*)(bias + ccol + 4);
#pragma unroll
    for (int i = 0; i < 8; i++) {
        float4 o0, o1;
        o0.x = acc[i][0] + bb0.x; o0.y = acc[i][1] + bb0.y;
        o0.z = acc[i][2] + bb0.z; o0.w = acc[i][3] + bb0.w;
        o1.x = acc[i][4] + bb1.x; o1.y = acc[i][5] + bb1.y;
        o1.z = acc[i][6] + bb1.z; o1.w = acc[i][7] + bb1.w;
        *(float4*)(g_h + (size_t)(crow + i) * NO + ccol) = o0;
        *(float4*)(g_h + (size_t)(crow + i) * NO + ccol + 4) = o1;
    }
}

// ------------------------- BN column stats (2-stage, deterministic) ----------
__global__ __launch_bounds__(512) void stats_partial_kernel() {
    int c = threadIdx.x;
    int blk = blockIdx.x;
    float s = 0.f, s2 = 0.f;
    int r0 = blk * 512;
    for (int r = 0; r < 512; r++) {
        float v = g_h[(size_t)(r0 + r) * NO + c];
        s += v;
        s2 = fmaf(v, v, s2);
    }
    g_part[blk * NO + c] = s;
    g_part[128 * NO + blk * NO + c] = s2;
}

__global__ __launch_bounds__(512) void stats_final_kernel(const float* __restrict__ gamma,
                                                          const float* __restrict__ beta) {
    int c = threadIdx.x;
    float s = 0.f, s2 = 0.f;
    for (int b = 0; b < 128; b++) {
        s  += g_part[b * NO + c];
        s2 += g_part[128 * NO + b * NO + c];
    }
    float inv = 1.0f / (float)NPTS;
    float mu  = s * inv;
    float var = s2 * inv - mu * mu;
    float a = gamma[c] * rsqrtf(var + 1e-5f);
    g_a[c] = a;
    g_c[c] = beta[c] - mu * a;
}

// ------------------------- fused KNN score-GEMM + top-16 ---------------------
// score = q.x - 0.5|x|^2  (maximize == minimize squared distance)
// grid: (8 query-tiles, 4 point-segments, 16 clouds); 256 thr; 128x128 tiles.
__global__ __launch_bounds__(256, 2) void knn_kernel(const float* __restrict__ feat) {
    extern __shared__ float sm[];
    float* Qs   = sm;                     // 8*128
    float* Xs   = Qs + 8 * 128;           // 8*128
    float* Sc   = Xs + 8 * 128;           // 128*129 (pitch 129: conflict-free col reads)
    float* hn   = Sc + 128 * 129;         // 128
    float* topv = hn + 128;               // 128*16
    int*   topi = (int*)(topv + 128 * 16);// 128*16
    int*   qrow = topi + 128 * 16;        // 128

    const int qt = blockIdx.x, sg = blockIdx.y, cloud = blockIdx.z;
    const int tid = threadIdx.x;
    const int tx = tid & 15, ty = tid >> 4;

    if (tid < 128) {
        qrow[tid] = g_fps[cloud * NS + qt * 128 + tid];
#pragma unroll
        for (int r = 0; r < NK; r++) {
            topv[tid * NK + r] = NEG_INF;
            topi[tid * NK + r] = 0x7fffffff;
        }
    }
    __syncthreads();

    const int arow = tid >> 1, acol = (tid & 1) * 4;
    const float* qptr = feat + (size_t)qrow[arow] * NF;
    const int xcloudbase = cloud * NP + sg * PSEG;

    for (int pt = 0; pt < PSEG; pt += 128) {
        const int xbase = xcloudbase + pt;
        if (tid < 128) hn[tid] = g_hn[xbase + tid];
        const float* xptr = feat + (size_t)(xbase + arow) * NF;

        float acc[8][8];
#pragma unroll
        for (int i = 0; i < 8; i++)
#pragma unroll
            for (int j = 0; j < 8; j++) acc[i][j] = 0.f;

        for (int kb = 0; kb < NF; kb += 8) {
            float4 qv = *(const float4*)(qptr + kb + acol);
            Qs[(acol + 0) * 128 + arow] = qv.x;
            Qs[(acol + 1) * 128 + arow] = qv.y;
            Qs[(acol + 2) * 128 + arow] = qv.z;
            Qs[(acol + 3) * 128 + arow] = qv.w;
            float4 xv = *(const float4*)(xptr + kb + acol);
            Xs[(acol + 0) * 128 + arow] = xv.x;
            Xs[(acol + 1) * 128 + arow] = xv.y;
            Xs[(acol + 2) * 128 + arow] = xv.z;
            Xs[(acol + 3) * 128 + arow] = xv.w;
            __syncthreads();
#pragma unroll
            for (int k = 0; k < 8; k++) {
                float4 a0 = *(const float4*)&Qs[k * 128 + ty * 8];
                float4 a1 = *(const float4*)&Qs[k * 128 + ty * 8 + 4];
                float4 b0 = *(const float4*)&Xs[k * 128 + tx * 8];
                float4 b1 = *(const float4*)&Xs[k * 128 + tx * 8 + 4];
                float ar[8] = {a0.x, a0.y, a0.z, a0.w, a1.x, a1.y, a1.z, a1.w};
                float br[8] = {b0.x, b0.y, b0.z, b0.w, b1.x, b1.y, b1.z, b1.w};
#pragma unroll
                for (int i = 0; i < 8; i++)
#pragma unroll
                    for (int j = 0; j < 8; j++) acc[i][j] = fmaf(ar[i], br[j], acc[i][j]);
            }
            __syncthreads();
        }

#pragma unroll
        for (int i = 0; i < 8; i++)
#pragma unroll
            for (int j = 0; j < 8; j++)
                Sc[(ty * 8 + i) * 129 + tx * 8 + j] = acc[i][j];
        __syncthreads();

        // running top-16 insertion (1 thread per query; threshold cached in regs)
        if (tid < 128) {
            const int q = tid;
            const float* scr = Sc + q * 129;
            float* tv = topv + q * NK;
            int*   ti = topi + q * NK;
            float th = tv[NK - 1];
            int  thi = ti[NK - 1];
            for (int p = 0; p < 128; p++) {
                float s = scr[p] - hn[p];
                int gi = xbase + p;
                if (s > th || (s == th && gi < thi)) {
                    int r = NK - 1;
                    while (r > 0) {
                        float pv = tv[r - 1];
                        int   pi = ti[r - 1];
                        if (s > pv || (s == pv && gi < pi)) {
                            tv[r] = pv; ti[r] = pi; r--;
                        } else break;
                    }
                    tv[r] = s; ti[r] = gi;
                    th = tv[NK - 1]; thi = ti[NK - 1];
                }
            }
        }
        __syncthreads();
    }

    if (tid < 128) {
        int q = cloud * NS + qt * 128 + tid;
#pragma unroll
        for (int r = 0; r < NK; r++) {
            g_knnv[((size_t)q * SEG + sg) * NK + r] = topv[tid * NK + r];
            g_knni[((size_t)q * SEG + sg) * NK + r] = topi[tid * NK + r];
        }
    }
}

// ------------------------- merge per-segment top-16 lists --------------------
__global__ __launch_bounds__(256) void merge_kernel() {
    int q = blockIdx.x * 256 + threadIdx.x;
    if (q >= NQ) return;
    const float* v  = g_knnv + (size_t)q * SEG * NK;
    const int*   ii = g_knni + (size_t)q * SEG * NK;
    unsigned long long used = 0ull;
    for (int r = 0; r < NK; r++) {
        float bv = NEG_INF;
        int bi = 0x7fffffff, bs = 0;
        for (int j = 0; j < SEG * NK; j++) {
            if ((used >> j) & 1ull) continue;
            float vv = v[j];
            int   vi = ii[j];
            if (vv > bv || (vv == bv && vi < bi)) { bv = vv; bi = vi; bs = j; }
        }
        used |= 1ull << bs;
        g_nn[(size_t)q * NK + r] = bi;
    }
}

// ------------------------- gather + max-pool + BN + ReLU ---------------------
// max_k relu(a*h_k + c) == relu(max(a*hmax + c, a*hmin + c))  (any sign of a)
__global__ __launch_bounds__(128) void gather_kernel(float* __restrict__ out) {
    __shared__ int nn[NK];
    const int q = blockIdx.x;
    const int tid = threadIdx.x;
    if (tid < NK) nn[tid] = g_nn[(size_t)q * NK + tid];
    __syncthreads();

    float mx0 = NEG_INF, mx1 = NEG_INF, mx2 = NEG_INF, mx3 = NEG_INF;
    float mn0 = POS_INF, mn1 = POS_INF, mn2 = POS_INF, mn3 = POS_INF;
#pragma unroll
    for (int n = 0; n < NK; n++) {
        const float* hp = g_h + (size_t)nn[n] * NO;
        float v0 = hp[tid], v1 = hp[tid + 128], v2 = hp[tid + 256], v3 = hp[tid + 384];
        mx0 = fmaxf(mx0, v0); mn0 = fminf(mn0, v0);
        mx1 = fmaxf(mx1, v1); mn1 = fminf(mn1, v1);
        mx2 = fmaxf(mx2, v2); mn2 = fminf(mn2, v2);
        mx3 = fmaxf(mx3, v3); mn3 = fminf(mn3, v3);
    }
    float* op = out + (size_t)q * NO;
#pragma unroll
    for (int j = 0; j < 4; j++) {
        int c = tid + j * 128;
        float mx = (j == 0) ? mx0 : (j == 1) ? mx1 : (j == 2) ? mx2 : mx3;
        float mn = (j == 0) ? mn0 : (j == 1) ? mn1 : (j == 2) ? mn2 : mn3;
        float a = g_a[c], cc = g_c[c];
        float o = fmaxf(fmaf(a, mx, cc), fmaf(a, mn, cc));
        op[c] = fmaxf(o, 0.0f);
    }
}

// ------------------------- launch --------------------------------------------
#define FPS_SMEM ((NP * 3 + NS + 16 + 16 + 1) * 4)
#define KNN_SMEM ((8 * 128 * 2 + 128 * 129 + 128 + 128 * 16 * 2 + 128) * 4)

extern "C" void kernel_launch(void* const* d_in, const int* in_sizes, int n_in,
                              void* d_out, int out_size) {
    (void)in_sizes; (void)n_in; (void)out_size;
    const float* features  = (const float*)d_in[0];
    const float* positions = (const float*)d_in[1];
    const int*   batch     = (const int*)d_in[2];
    const float* W         = (const float*)d_in[3];
    const float* bias      = (const float*)d_in[4];
    const float* gamma     = (const float*)d_in[5];
    const float* beta      = (const float*)d_in[6];

    float* out       = (float*)d_out;
    float* out_feat  = out;
    float* out_pos   = out + (size_t)NQ * NO;
    float* out_batch = out_pos + (size_t)NQ * 3;

    cudaFuncSetAttribute(fps_kernel, cudaFuncAttributeMaxDynamicSharedMemorySize, FPS_SMEM);
    cudaFuncSetAttribute(knn_kernel, cudaFuncAttributeMaxDynamicSharedMemorySize, KNN_SMEM);

    fps_kernel<<<NB, 512, FPS_SMEM>>>(positions, batch, out_pos, out_batch);
    xnorm_kernel<<<NPTS / 4, 128>>>(features);
    gemm_h_kernel<<<dim3(4, 512), 256>>>(features, W, bias);
    stats_partial_kernel<<<128, 512>>>();
    stats_final_kernel<<<1, 512>>>(gamma, beta);
    knn_kernel<<<dim3(8, SEG, NB), 256, KNN_SMEM>>>(features);
    merge_kernel<<<NQ / 256, 256>>>();
    gather_kernel<<<NQ, 128>>>(out_feat);
}

// round 2
// speedup vs baseline: 1.0002x; 1.0002x over previous
#include <cuda_runtime.h>
#include <cstdint>
#include <cstddef>

// Problem constants
#define NB 16
#define NP 4096
#define NS 1024
#define NK 16
#define NF 256
#define NO 512
#define NPTS (NB*NP)   // 65536
#define NQ   (NB*NS)   // 16384
#define SEG  4
#define PSEG (NP/SEG)  // 1024

#define POS_INF __int_as_float(0x7f800000)
#define NEG_INF __int_as_float(0xff800000)

// ------------------------- scratch (static device globals) -------------------
__device__ float g_h[(size_t)NPTS * NO];      // 128MB: h = XW + b
__device__ float g_hn[NPTS];                  // 0.5*|x|^2 per point (feature space)
__device__ int   g_fps[NQ];                   // global fps indices
__device__ float g_part[2 * 128 * NO];        // column partial sums / sumsq
__device__ float g_a[NO];                     // BN scale  a = gamma*rsqrt(var+eps)
__device__ float g_c[NO];                     // BN shift  c = beta - mu*a
__device__ float g_knnv[(size_t)NQ * SEG * NK];
__device__ int   g_knni[(size_t)NQ * SEG * NK];
__device__ int   g_nn[(size_t)NQ * NK];

// ------------------------- FPS: one block per cloud --------------------------
// Bit-exact vs jax reference: d = (dx*dx + dy*dy) + dz*dz with RN mul/add
// (no FMA contraction), fminf accumulation, argmax with first-index tiebreak.
__global__ __launch_bounds__(512) void fps_kernel(const float* __restrict__ positions,
                                                  const int* __restrict__ batch,
                                                  float* __restrict__ out_pos,
                                                  float* __restrict__ out_batch) {
    extern __shared__ float sm[];
    float* spos  = sm;                          // NP*3 floats
    int*   sel   = (int*)(spos + NP * 3);       // NS
    float* rv    = (float*)(sel + NS);          // 16
    int*   ri    = (int*)(rv + 16);             // 16
    int*   slast = ri + 16;                     // 1

    const int cloud = blockIdx.x;
    const int tid = threadIdx.x;
    const float* pos = positions + (size_t)cloud * NP * 3;

    for (int i = tid; i < NP * 3; i += 512) spos[i] = pos[i];
    __syncthreads();

    const int PPT = NP / 512;  // 8 points per thread
    float px[8], py[8], pz[8], md[8];
#pragma unroll
    for (int j = 0; j < PPT; j++) {
        int pt = tid + j * 512;
        px[j] = spos[pt * 3 + 0];
        py[j] = spos[pt * 3 + 1];
        pz[j] = spos[pt * 3 + 2];
        md[j] = POS_INF;
    }
    if (tid == 0) sel[0] = 0;
    int last = 0;
    const int lane = tid & 31, warp = tid >> 5;

    for (int it = 1; it < NS; it++) {
        float lx = spos[last * 3 + 0];
        float ly = spos[last * 3 + 1];
        float lz = spos[last * 3 + 2];
        float bv = NEG_INF;
        int bi = 0x7fffffff;
#pragma unroll
        for (int j = 0; j < PPT; j++) {
            float dx = px[j] - lx, dy = py[j] - ly, dz = pz[j] - lz;
            float d = __fadd_rn(__fadd_rn(__fmul_rn(dx, dx), __fmul_rn(dy, dy)),
                                __fmul_rn(dz, dz));
            float m = fminf(md[j], d);
            md[j] = m;
            // pt ascends with j -> strict > keeps smallest index on in-thread tie
            if (m > bv) { bv = m; bi = tid + j * 512; }
        }
#pragma unroll
        for (int off = 16; off > 0; off >>= 1) {
            float ov = __shfl_down_sync(0xffffffffu, bv, off);
            int   oi = __shfl_down_sync(0xffffffffu, bi, off);
            if (ov > bv || (ov == bv && oi < bi)) { bv = ov; bi = oi; }
        }
        if (lane == 0) { rv[warp] = bv; ri[warp] = bi; }
        __syncthreads();
        if (tid == 0) {
            float v = rv[0]; int b = ri[0];
#pragma unroll
            for (int w = 1; w < 16; w++) {
                if (rv[w] > v || (rv[w] == v && ri[w] < b)) { v = rv[w]; b = ri[w]; }
            }
            sel[it] = b;
            slast[0] = b;
        }
        __syncthreads();
        last = slast[0];
    }

    // Emit fps indices + sampled positions + batch (as float)
    for (int s = tid; s < NS; s += 512) {
        int loc = sel[s];
        int g = cloud * NP + loc;
        int oq = cloud * NS + s;
        g_fps[oq] = g;
        out_pos[oq * 3 + 0] = spos[loc * 3 + 0];
        out_pos[oq * 3 + 1] = spos[loc * 3 + 1];
        out_pos[oq * 3 + 2] = spos[loc * 3 + 2];
        out_batch[oq] = (float)batch[g];
    }
}

// ------------------------- 0.5*|x|^2 per point (feature space) ---------------
__global__ __launch_bounds__(128) void xnorm_kernel(const float* __restrict__ feat) {
    int row = blockIdx.x * 4 + (threadIdx.x >> 5);
    int lane = threadIdx.x & 31;
    const float* f = feat + (size_t)row * NF;
    float s = 0.f;
#pragma unroll
    for (int i = 0; i < NF / 32; i++) {
        float v = f[lane + 32 * i];
        s = fmaf(v, v, s);
    }
#pragma unroll
    for (int off = 16; off > 0; off >>= 1) s += __shfl_down_sync(0xffffffffu, s, off);
    if (lane == 0) g_hn[row] = 0.5f * s;
}

// ------------------------- SGEMM h = X*W + b  (fp32, 128x128x8) --------------
__global__ __launch_bounds__(256) void gemm_h_kernel(const float* __restrict__ A,
                                                     const float* __restrict__ W,
                                                     const float* __restrict__ bias) {
    __shared__ float As[8][128];
    __shared__ float Bs[8][128];
    const int bx = blockIdx.x;  // 0..3   (N tiles)
    const int by = blockIdx.y;  // 0..511 (M tiles)
    const int tid = threadIdx.x;
    const int tx = tid & 15, ty = tid >> 4;
    const float* Ab = A + (size_t)by * 128 * NF;
    const int arow = tid >> 1, acol = (tid & 1) * 4;
    const int brow = tid >> 5, bcol = (tid & 31) * 4;

    float acc[8][8];
#pragma unroll
    for (int i = 0; i < 8; i++)
#pragma unroll
        for (int j = 0; j < 8; j++) acc[i][j] = 0.f;

    for (int kb = 0; kb < NF; kb += 8) {
        float4 av = *(const float4*)(Ab + (size_t)arow * NF + kb + acol);
        As[acol + 0][arow] = av.x;
        As[acol + 1][arow] = av.y;
        As[acol + 2][arow] = av.z;
        As[acol + 3][arow] = av.w;
        float4 bv = *(const float4*)(W + (size_t)(kb + brow) * NO + bx * 128 + bcol);
        *(float4*)&Bs[brow][bcol] = bv;
        __syncthreads();
#pragma unroll
        for (int k = 0; k < 8; k++) {
            float4 a0 = *(const float4*)&As[k][ty * 8];
            float4 a1 = *(const float4*)&As[k][ty * 8 + 4];
            float4 b0 = *(const float4*)&Bs[k][tx * 8];
            float4 b1 = *(const float4*)&Bs[k][tx * 8 + 4];
            float ar[8] = {a0.x, a0.y, a0.z, a0.w, a1.x, a1.y, a1.z, a1.w};
            float br[8] = {b0.x, b0.y, b0.z, b0.w, b1.x, b1.y, b1.z, b1.w};
#pragma unroll
            for (int i = 0; i < 8; i++)
#pragma unroll
                for (int j = 0; j < 8; j++) acc[i][j] = fmaf(ar[i], br[j], acc[i][j]);
        }
        __syncthreads();
    }

    const int ccol = bx * 128 + tx * 8;
    const int crow = by * 128 + ty * 8;
    float4 bb0 = *(const float4*)(bias + ccol);
    float4 bb1 = *(const float4*)(bias + ccol + 4);
#pragma unroll
    for (int i = 0; i < 8; i++) {
        float4 o0, o1;
        o0.x = acc[i][0] + bb0.x; o0.y = acc[i][1] + bb0.y;
        o0.z = acc[i][2] + bb0.z; o0.w = acc[i][3] + bb0.w;
        o1.x = acc[i][4] + bb1.x; o1.y = acc[i][5] + bb1.y;
        o1.z = acc[i][6] + bb1.z; o1.w = acc[i][7] + bb1.w;
        *(float4*)(g_h + (size_t)(crow + i) * NO + ccol) = o0;
        *(float4*)(g_h + (size_t)(crow + i) * NO + ccol + 4) = o1;
    }
}

// ------------------------- BN column stats (2-stage, deterministic) ----------
__global__ __launch_bounds__(512) void stats_partial_kernel() {
    int c = threadIdx.x;
    int blk = blockIdx.x;
    float s = 0.f, s2 = 0.f;
    int r0 = blk * 512;
    for (int r = 0; r < 512; r++) {
        float v = g_h[(size_t)(r0 + r) * NO + c];
        s += v;
        s2 = fmaf(v, v, s2);
    }
    g_part[blk * NO + c] = s;
    g_part[128 * NO + blk * NO + c] = s2;
}

__global__ __launch_bounds__(512) void stats_final_kernel(const float* __restrict__ gamma,
                                                          const float* __restrict__ beta) {
    int c = threadIdx.x;
    float s = 0.f, s2 = 0.f;
    for (int b = 0; b < 128; b++) {
        s  += g_part[b * NO + c];
        s2 += g_part[128 * NO + b * NO + c];
    }
    float inv = 1.0f / (float)NPTS;
    float mu  = s * inv;
    float var = s2 * inv - mu * mu;
    float a = gamma[c] * rsqrtf(var + 1e-5f);
    g_a[c] = a;
    g_c[c] = beta[c] - mu * a;
}

// ------------------------- fused KNN score-GEMM + top-16 ---------------------
// score = q.x - 0.5|x|^2  (maximize == minimize squared distance)
// grid: (8 query-tiles, 4 point-segments, 16 clouds); 256 thr; 128x128 tiles.
__global__ __launch_bounds__(256, 2) void knn_kernel(const float* __restrict__ feat) {
    extern __shared__ float sm[];
    float* Qs   = sm;                     // 8*128
    float* Xs   = Qs + 8 * 128;           // 8*128
    float* Sc   = Xs + 8 * 128;           // 128*129 (pitch 129: conflict-free col reads)
    float* hn   = Sc + 128 * 129;         // 128
    float* topv = hn + 128;               // 128*16
    int*   topi = (int*)(topv + 128 * 16);// 128*16
    int*   qrow = topi + 128 * 16;        // 128

    const int qt = blockIdx.x, sg = blockIdx.y, cloud = blockIdx.z;
    const int tid = threadIdx.x;
    const int tx = tid & 15, ty = tid >> 4;

    if (tid < 128) {
        qrow[tid] = g_fps[cloud * NS + qt * 128 + tid];
#pragma unroll
        for (int r = 0; r < NK; r++) {
            topv[tid * NK + r] = NEG_INF;
            topi[tid * NK + r] = 0x7fffffff;
        }
    }
    __syncthreads();

    const int arow = tid >> 1, acol = (tid & 1) * 4;
    const float* qptr = feat + (size_t)qrow[arow] * NF;
    const int xcloudbase = cloud * NP + sg * PSEG;

    for (int pt = 0; pt < PSEG; pt += 128) {
        const int xbase = xcloudbase + pt;
        if (tid < 128) hn[tid] = g_hn[xbase + tid];
        const float* xptr = feat + (size_t)(xbase + arow) * NF;

        float acc[8][8];
#pragma unroll
        for (int i = 0; i < 8; i++)
#pragma unroll
            for (int j = 0; j < 8; j++) acc[i][j] = 0.f;

        for (int kb = 0; kb < NF; kb += 8) {
            float4 qv = *(const float4*)(qptr + kb + acol);
            Qs[(acol + 0) * 128 + arow] = qv.x;
            Qs[(acol + 1) * 128 + arow] = qv.y;
            Qs[(acol + 2) * 128 + arow] = qv.z;
            Qs[(acol + 3) * 128 + arow] = qv.w;
            float4 xv = *(const float4*)(xptr + kb + acol);
            Xs[(acol + 0) * 128 + arow] = xv.x;
            Xs[(acol + 1) * 128 + arow] = xv.y;
            Xs[(acol + 2) * 128 + arow] = xv.z;
            Xs[(acol + 3) * 128 + arow] = xv.w;
            __syncthreads();
#pragma unroll
            for (int k = 0; k < 8; k++) {
                float4 a0 = *(const float4*)&Qs[k * 128 + ty * 8];
                float4 a1 = *(const float4*)&Qs[k * 128 + ty * 8 + 4];
                float4 b0 = *(const float4*)&Xs[k * 128 + tx * 8];
                float4 b1 = *(const float4*)&Xs[k * 128 + tx * 8 + 4];
                float ar[8] = {a0.x, a0.y, a0.z, a0.w, a1.x, a1.y, a1.z, a1.w};
                float br[8] = {b0.x, b0.y, b0.z, b0.w, b1.x, b1.y, b1.z, b1.w};
#pragma unroll
                for (int i = 0; i < 8; i++)
#pragma unroll
                    for (int j = 0; j < 8; j++) acc[i][j] = fmaf(ar[i], br[j], acc[i][j]);
            }
            __syncthreads();
        }

#pragma unroll
        for (int i = 0; i < 8; i++)
#pragma unroll
            for (int j = 0; j < 8; j++)
                Sc[(ty * 8 + i) * 129 + tx * 8 + j] = acc[i][j];
        __syncthreads();

        // running top-16 insertion (1 thread per query; threshold cached in regs)
        if (tid < 128) {
            const int q = tid;
            const float* scr = Sc + q * 129;
            float* tv = topv + q * NK;
            int*   ti = topi + q * NK;
            float th = tv[NK - 1];
            int  thi = ti[NK - 1];
            for (int p = 0; p < 128; p++) {
                float s = scr[p] - hn[p];
                int gi = xbase + p;
                if (s > th || (s == th && gi < thi)) {
                    int r = NK - 1;
                    while (r > 0) {
                        float pv = tv[r - 1];
                        int   pi = ti[r - 1];
                        if (s > pv || (s == pv && gi < pi)) {
                            tv[r] = pv; ti[r] = pi; r--;
                        } else break;
                    }
                    tv[r] = s; ti[r] = gi;
                    th = tv[NK - 1]; thi = ti[NK - 1];
                }
            }
        }
        __syncthreads();
    }

    if (tid < 128) {
        int q = cloud * NS + qt * 128 + tid;
#pragma unroll
        for (int r = 0; r < NK; r++) {
            g_knnv[((size_t)q * SEG + sg) * NK + r] = topv[tid * NK + r];
            g_knni[((size_t)q * SEG + sg) * NK + r] = topi[tid * NK + r];
        }
    }
}

// ------------------------- merge per-segment top-16 lists --------------------
__global__ __launch_bounds__(256) void merge_kernel() {
    int q = blockIdx.x * 256 + threadIdx.x;
    if (q >= NQ) return;
    const float* v  = g_knnv + (size_t)q * SEG * NK;
    const int*   ii = g_knni + (size_t)q * SEG * NK;
    unsigned long long used = 0ull;
    for (int r = 0; r < NK; r++) {
        float bv = NEG_INF;
        int bi = 0x7fffffff, bs = 0;
        for (int j = 0; j < SEG * NK; j++) {
            if ((used >> j) & 1ull) continue;
            float vv = v[j];
            int   vi = ii[j];
            if (vv > bv || (vv == bv && vi < bi)) { bv = vv; bi = vi; bs = j; }
        }
        used |= 1ull << bs;
        g_nn[(size_t)q * NK + r] = bi;
    }
}

// ------------------------- gather + max-pool + BN + ReLU ---------------------
// max_k relu(a*h_k + c) == relu(max(a*hmax + c, a*hmin + c))  (any sign of a)
__global__ __launch_bounds__(128) void gather_kernel(float* __restrict__ out) {
    __shared__ int nn[NK];
    const int q = blockIdx.x;
    const int tid = threadIdx.x;
    if (tid < NK) nn[tid] = g_nn[(size_t)q * NK + tid];
    __syncthreads();

    float mx0 = NEG_INF, mx1 = NEG_INF, mx2 = NEG_INF, mx3 = NEG_INF;
    float mn0 = POS_INF, mn1 = POS_INF, mn2 = POS_INF, mn3 = POS_INF;
#pragma unroll
    for (int n = 0; n < NK; n++) {
        const float* hp = g_h + (size_t)nn[n] * NO;
        float v0 = hp[tid], v1 = hp[tid + 128], v2 = hp[tid + 256], v3 = hp[tid + 384];
        mx0 = fmaxf(mx0, v0); mn0 = fminf(mn0, v0);
        mx1 = fmaxf(mx1, v1); mn1 = fminf(mn1, v1);
        mx2 = fmaxf(mx2, v2); mn2 = fminf(mn2, v2);
        mx3 = fmaxf(mx3, v3); mn3 = fminf(mn3, v3);
    }
    float* op = out + (size_t)q * NO;
#pragma unroll
    for (int j = 0; j < 4; j++) {
        int c = tid + j * 128;
        float mx = (j == 0) ? mx0 : (j == 1) ? mx1 : (j == 2) ? mx2 : mx3;
        float mn = (j == 0) ? mn0 : (j == 1) ? mn1 : (j == 2) ? mn2 : mn3;
        float a = g_a[c], cc = g_c[c];
        float o = fmaxf(fmaf(a, mx, cc), fmaf(a, mn, cc));
        op[c] = fmaxf(o, 0.0f);
    }
}

// ------------------------- launch --------------------------------------------
#define FPS_SMEM ((NP * 3 + NS + 16 + 16 + 1) * 4)
#define KNN_SMEM ((8 * 128 * 2 + 128 * 129 + 128 + 128 * 16 * 2 + 128) * 4)

extern "C" void kernel_launch(void* const* d_in, const int* in_sizes, int n_in,
                              void* d_out, int out_size) {
    (void)in_sizes; (void)n_in; (void)out_size;
    const float* features  = (const float*)d_in[0];
    const float* positions = (const float*)d_in[1];
    const int*   batch     = (const int*)d_in[2];
    const float* W         = (const float*)d_in[3];
    const float* bias      = (const float*)d_in[4];
    const float* gamma     = (const float*)d_in[5];
    const float* beta      = (const float*)d_in[6];

    float* out       = (float*)d_out;
    float* out_feat  = out;
    float* out_pos   = out + (size_t)NQ * NO;
    float* out_batch = out_pos + (size_t)NQ * 3;

    cudaFuncSetAttribute(fps_kernel, cudaFuncAttributeMaxDynamicSharedMemorySize, FPS_SMEM);
    cudaFuncSetAttribute(knn_kernel, cudaFuncAttributeMaxDynamicSharedMemorySize, KNN_SMEM);

    fps_kernel<<<NB, 512, FPS_SMEM>>>(positions, batch, out_pos, out_batch);
    xnorm_kernel<<<NPTS / 4, 128>>>(features);
    gemm_h_kernel<<<dim3(4, 512), 256>>>(features, W, bias);
    stats_partial_kernel<<<128, 512>>>();
    stats_final_kernel<<<1, 512>>>(gamma, beta);
    knn_kernel<<<dim3(8, SEG, NB), 256, KNN_SMEM>>>(features);
    merge_kernel<<<NQ / 256, 256>>>();
    gather_kernel<<<NQ, 128>>>(out_feat);
}